// round 1
// baseline (speedup 1.0000x reference)
#include <cuda_runtime.h>
#include <math.h>

#define BB 1024
#define DIMC 384
#define NN 49
#define HEADS 8
#define KD 32
#define DV 128
#define DHC 1024
#define CQKV 1536

// ---------------- scratch (static device allocations) ----------------
__device__ float g_w[CQKV * DIMC];              // fused qkv weights (BN + scale folded)
__device__ float g_bias[CQKV];
__device__ float g_pw[DIMC * DHC];              // fused proj weights
__device__ float g_pb[DIMC];
__device__ float g_vlw[DHC * 9];                // fused depthwise weights
__device__ float g_vlb[DHC];
__device__ float g_qkv[(size_t)BB * CQKV * NN];     // 308 MB
__device__ float g_attn[(size_t)BB * HEADS * NN * NN]; // 79 MB
__device__ float g_hidden[(size_t)BB * DHC * NN];   // 205 MB

// ---------------- f32x2 helpers (Blackwell packed fp32) ----------------
__device__ __forceinline__ void fma2(unsigned long long& d, unsigned long long a,
                                     unsigned long long b) {
    asm("fma.rn.f32x2 %0, %1, %2, %0;" : "+l"(d) : "l"(a), "l"(b));
}
__device__ __forceinline__ unsigned long long pack2(float x) {
    unsigned long long r;
    unsigned u = __float_as_uint(x);
    asm("mov.b64 %0, {%1, %1};" : "=l"(r) : "r"(u));
    return r;
}

// ---------------- prep: fold BN affines / scales into weights ----------------
__global__ void prep_kernel(const float* __restrict__ qw, const float* __restrict__ qb,
                            const float* __restrict__ qs, const float* __restrict__ qo,
                            const float* __restrict__ kw, const float* __restrict__ kb,
                            const float* __restrict__ ks, const float* __restrict__ ko,
                            const float* __restrict__ vw, const float* __restrict__ vb,
                            const float* __restrict__ vs, const float* __restrict__ vo,
                            const float* __restrict__ vlw, const float* __restrict__ vlb,
                            const float* __restrict__ vls, const float* __restrict__ vlo,
                            const float* __restrict__ pw, const float* __restrict__ pb,
                            const float* __restrict__ ps, const float* __restrict__ po) {
    int i = blockIdx.x * blockDim.x + threadIdx.x;
    const float SCALE = 0.17677669529663687f;  // 32^-0.5, folded into q
    if (i < CQKV * DIMC) {
        int o = i / DIMC, c = i - o * DIMC;
        float v;
        if (o < 256)       v = qw[o * DIMC + c] * qs[o] * SCALE;
        else if (o < 512)  { int oo = o - 256; v = kw[oo * DIMC + c] * ks[oo]; }
        else               { int oo = o - 512; v = vw[oo * DIMC + c] * vs[oo]; }
        g_w[i] = v;
    }
    if (i < CQKV) {
        float v;
        if (i < 256)       v = (qb[i] * qs[i] + qo[i]) * SCALE;
        else if (i < 512)  { int oo = i - 256; v = kb[oo] * ks[oo] + ko[oo]; }
        else               { int oo = i - 512; v = vb[oo] * vs[oo] + vo[oo]; }
        g_bias[i] = v;
    }
    if (i < DIMC * DHC) { int o = i / DHC; g_pw[i] = pw[i] * ps[o]; }
    if (i < DIMC)  g_pb[i] = pb[i] * ps[i] + po[i];
    if (i < DHC * 9) { int c = i / 9; g_vlw[i] = vlw[i] * vls[c]; }
    if (i < DHC)   g_vlb[i] = vlb[i] * vls[i] + vlo[i];
}

// ---------------- GEMM: Y[b,o,n] = sum_c W[o,c]*X[b,c,n] + bias[o] ----------------
// block: 224 threads, tile = 128 O x 49 N, thread tile = 4 O x 8 N (f32x2 packed)
__global__ __launch_bounds__(224) void gemm_kernel(const float* __restrict__ W,
                                                   const float* __restrict__ bias,
                                                   const float* __restrict__ X,
                                                   float* __restrict__ Y, int O, int K) {
    __shared__ __align__(16) float xs[32][56];
    __shared__ __align__(16) float ws[128][32];
    int b = blockIdx.y;
    int obase = blockIdx.x * 128;
    const float* Xb = X + (size_t)b * K * NN;
    float* Yb = Y + (size_t)b * O * NN;
    int tid = threadIdx.x;
    int og = tid / 7, ng = tid - og * 7;  // og 0..31, ng 0..6
    int o0 = og * 4, n0 = ng * 8;
    unsigned long long acc[4][4];
#pragma unroll
    for (int a = 0; a < 4; a++)
#pragma unroll
        for (int p = 0; p < 4; p++) acc[a][p] = 0ULL;

    for (int c0 = 0; c0 < K; c0 += 32) {
        for (int idx = tid; idx < 1024; idx += 224) {
            int o = idx >> 3, c4 = (idx & 7) << 2;
            *(float4*)&ws[o][c4] = *(const float4*)&W[(size_t)(obase + o) * K + c0 + c4];
        }
        for (int idx = tid; idx < 32 * 56; idx += 224) {
            int cc = idx / 56, n = idx - cc * 56;
            xs[cc][n] = (n < NN) ? Xb[(size_t)(c0 + cc) * NN + n] : 0.f;
        }
        __syncthreads();
#pragma unroll
        for (int cc = 0; cc < 32; cc++) {
            ulonglong2 xa = *(const ulonglong2*)&xs[cc][n0];
            ulonglong2 xb2 = *(const ulonglong2*)&xs[cc][n0 + 4];
#pragma unroll
            for (int oo = 0; oo < 4; oo++) {
                unsigned long long wp = pack2(ws[o0 + oo][cc]);
                fma2(acc[oo][0], wp, xa.x);
                fma2(acc[oo][1], wp, xa.y);
                fma2(acc[oo][2], wp, xb2.x);
                fma2(acc[oo][3], wp, xb2.y);
            }
        }
        __syncthreads();
    }
#pragma unroll
    for (int oo = 0; oo < 4; oo++) {
        int o = obase + o0 + oo;
        float bv = bias[o];
        float vals[8];
#pragma unroll
        for (int p = 0; p < 4; p++) {
            vals[2 * p]     = __uint_as_float((unsigned)(acc[oo][p] & 0xffffffffULL)) + bv;
            vals[2 * p + 1] = __uint_as_float((unsigned)(acc[oo][p] >> 32)) + bv;
        }
#pragma unroll
        for (int q = 0; q < 8; q++) {
            int n = n0 + q;
            if (n < NN) Yb[(size_t)o * NN + n] = vals[q];
        }
    }
}

// ---------------- attention core: scores+bias -> th1 -> softmax -> th2 ----------------
// one block per batch, everything in shared memory (177 KB dynamic)
__global__ __launch_bounds__(256) void attn_kernel(const float* __restrict__ ab,
                                                   const float* __restrict__ th1w_g,
                                                   const float* __restrict__ th1b_g,
                                                   const float* __restrict__ th2w_g,
                                                   const float* __restrict__ th2b_g) {
    extern __shared__ float sm[];
    float* r1 = sm;                 // 25088 floats: q/k, later reused for th1 output
    float* r2 = sm + 25088;         // 19208 floats: raw scores
    float* abs_ = sm + 44296;       // 392
    float* t1w = abs_ + 392;        // 64
    float* t1b = t1w + 64;          // 8
    float* t2w = t1b + 8;           // 64
    float* t2b = t2w + 64;          // 8
    int b = blockIdx.x;
    int tid = threadIdx.x;
    const float* qkbase = g_qkv + (size_t)b * CQKV * NN;  // channels 0..511 = q,k

    for (int i = tid; i < (512 * NN) / 4; i += 256)
        ((float4*)r1)[i] = ((const float4*)qkbase)[i];
    for (int i = tid; i < 392; i += 256) abs_[i] = ab[i];
    if (tid < 64) { t1w[tid] = th1w_g[tid]; t2w[tid] = th2w_g[tid]; }
    if (tid < 8)  { t1b[tid] = th1b_g[tid]; t2b[tid] = th2b_g[tid]; }
    __syncthreads();

    // scores: r2[h,n,m] = q·k (scale folded into q) + rel-pos bias
    for (int p = tid; p < HEADS * NN; p += 256) {
        int h = p / NN, n = p - h * NN;
        float qv[KD];
#pragma unroll
        for (int kd = 0; kd < KD; kd++) qv[kd] = r1[(h * KD + kd) * NN + n];
        int ny = n / 7, nx = n - ny * 7;
        const float* kb_ = r1 + (256 + h * KD) * NN;
        float* srow = r2 + (size_t)h * NN * NN + n * NN;
        const float* abh = abs_ + h * NN;
        for (int m = 0; m < NN; m++) {
            float s = 0.f;
#pragma unroll
            for (int kd = 0; kd < KD; kd++) s += qv[kd] * kb_[kd * NN + m];
            int my = m / 7, mx = m - my * 7;
            int ridx = abs(ny - my) * 7 + abs(nx - mx);
            srow[m] = s + abh[ridx];
        }
    }
    __syncthreads();

    // th1 head mix -> r1 (q/k space reused)
    for (int p = tid; p < HEADS * NN; p += 256) {
        int i = p / NN, n = p - i * NN;
        float w[8];
#pragma unroll
        for (int j = 0; j < 8; j++) w[j] = t1w[i * 8 + j];
        float bi = t1b[i];
        const float* base = r2 + n * NN;
        float* orow = r1 + (size_t)p * NN;  // i*2401 + n*49
        for (int m = 0; m < NN; m++) {
            float s = bi;
#pragma unroll
            for (int j = 0; j < 8; j++) s += w[j] * base[j * 2401 + m];
            orow[m] = s;
        }
    }
    __syncthreads();

    // softmax in place (rows of 49)
    for (int p = tid; p < HEADS * NN; p += 256) {
        float* row = r1 + (size_t)p * NN;
        float mx = row[0];
        for (int m = 1; m < NN; m++) mx = fmaxf(mx, row[m]);
        float sum = 0.f;
        for (int m = 0; m < NN; m++) { float e = __expf(row[m] - mx); row[m] = e; sum += e; }
        float inv = 1.f / sum;
        for (int m = 0; m < NN; m++) row[m] *= inv;
    }
    __syncthreads();

    // th2 head mix -> global
    float* gout = g_attn + (size_t)b * HEADS * NN * NN;
    for (int p = tid; p < HEADS * NN; p += 256) {
        int i = p / NN, n = p - i * NN;
        float w[8];
#pragma unroll
        for (int j = 0; j < 8; j++) w[j] = t2w[i * 8 + j];
        float bi = t2b[i];
        const float* base = r1 + n * NN;
        float* orow = gout + (size_t)i * 2401 + n * NN;
        for (int m = 0; m < NN; m++) {
            float s = bi;
#pragma unroll
            for (int j = 0; j < 8; j++) s += w[j] * base[j * 2401 + m];
            orow[m] = s;
        }
    }
}

// ---------------- attn@V + depthwise conv + GELU -> hidden ----------------
// block per (head, batch), 224 threads: 32 d-groups(4) x 7 rows(y)
__global__ __launch_bounds__(224) void out_kernel() {
    __shared__ __align__(16) float as_[NN][NN];
    __shared__ __align__(16) float vs_[DV][NN];
    int h = blockIdx.x, b = blockIdx.y;
    int tid = threadIdx.x;
    const float* ap = g_attn + ((size_t)b * HEADS + h) * NN * NN;
    const float* vp = g_qkv + (size_t)b * CQKV * NN + (size_t)(512 + h * DV) * NN;
    for (int i = tid; i < NN * NN; i += 224) ((float*)as_)[i] = ap[i];
    for (int i = tid; i < (DV * NN) / 4; i += 224) ((float4*)vs_)[i] = ((const float4*)vp)[i];
    __syncthreads();

    int dg = tid / 7, y = tid - dg * 7;  // dg 0..31, y 0..6 (spatial row)
    int d0 = dg * 4;
    float acc[7][4];
#pragma unroll
    for (int x = 0; x < 7; x++)
#pragma unroll
        for (int j = 0; j < 4; j++) acc[x][j] = 0.f;

    for (int m = 0; m < NN; m++) {
        float a[7];
#pragma unroll
        for (int x = 0; x < 7; x++) a[x] = as_[y * 7 + x][m];
#pragma unroll
        for (int j = 0; j < 4; j++) {
            float v = vs_[d0 + j][m];
#pragma unroll
            for (int x = 0; x < 7; x++) acc[x][j] += a[x] * v;
        }
    }

    float* hb = g_hidden + (size_t)b * DHC * NN + (size_t)(h * DV) * NN;
#pragma unroll
    for (int j = 0; j < 4; j++) {
        int d = d0 + j;
        int c = h * DV + d;
        float wv[9];
#pragma unroll
        for (int k2 = 0; k2 < 9; k2++) wv[k2] = g_vlw[c * 9 + k2];
        float vb_ = g_vlb[c];
#pragma unroll
        for (int x = 0; x < 7; x++) {
            float vl = vb_;
#pragma unroll
            for (int dy = -1; dy <= 1; dy++) {
                int yy = y + dy;
                if (yy < 0 || yy >= 7) continue;
#pragma unroll
                for (int dx = -1; dx <= 1; dx++) {
                    int xx = x + dx;
                    if (xx < 0 || xx >= 7) continue;
                    vl += wv[(dy + 1) * 3 + (dx + 1)] * vs_[d][yy * 7 + xx];
                }
            }
            float o = acc[x][j] + vl;
            o = o * normcdff(o);  // exact GELU
            hb[(size_t)d * NN + y * 7 + x] = o;
        }
    }
}

// ---------------- host ----------------
extern "C" void kernel_launch(void* const* d_in, const int* in_sizes, int n_in,
                              void* d_out, int out_size) {
    const float* x    = (const float*)d_in[0];
    const float* qw   = (const float*)d_in[1];
    const float* qb   = (const float*)d_in[2];
    const float* qs   = (const float*)d_in[3];
    const float* qo   = (const float*)d_in[4];
    const float* kw   = (const float*)d_in[5];
    const float* kb   = (const float*)d_in[6];
    const float* ks   = (const float*)d_in[7];
    const float* ko   = (const float*)d_in[8];
    const float* vw   = (const float*)d_in[9];
    const float* vb   = (const float*)d_in[10];
    const float* vs   = (const float*)d_in[11];
    const float* vo   = (const float*)d_in[12];
    const float* vlw  = (const float*)d_in[13];
    const float* vlb  = (const float*)d_in[14];
    const float* vls  = (const float*)d_in[15];
    const float* vlo  = (const float*)d_in[16];
    const float* th1w = (const float*)d_in[17];
    const float* th1b = (const float*)d_in[18];
    const float* th2w = (const float*)d_in[19];
    const float* th2b = (const float*)d_in[20];
    const float* pw   = (const float*)d_in[21];
    const float* pb   = (const float*)d_in[22];
    const float* ps   = (const float*)d_in[23];
    const float* po   = (const float*)d_in[24];
    const float* ab   = (const float*)d_in[25];

    void *pgw, *pgbias, *pgpw, *pgpb, *pgqkv, *pghid;
    cudaGetSymbolAddress(&pgw, g_w);
    cudaGetSymbolAddress(&pgbias, g_bias);
    cudaGetSymbolAddress(&pgpw, g_pw);
    cudaGetSymbolAddress(&pgpb, g_pb);
    cudaGetSymbolAddress(&pgqkv, g_qkv);
    cudaGetSymbolAddress(&pghid, g_hidden);

    static int smem_set = 0;
    (void)smem_set;
    cudaFuncSetAttribute(attn_kernel, cudaFuncAttributeMaxDynamicSharedMemorySize, 179328);

    // 1. fold affines into weights
    prep_kernel<<<(CQKV * DIMC + 255) / 256, 256>>>(qw, qb, qs, qo, kw, kb, ks, ko,
                                                    vw, vb, vs, vo, vlw, vlb, vls, vlo,
                                                    pw, pb, ps, po);
    // 2. fused QKV projection (1536 x 49 per batch, K=384)
    gemm_kernel<<<dim3(12, BB), 224>>>((const float*)pgw, (const float*)pgbias, x,
                                       (float*)pgqkv, CQKV, DIMC);
    // 3. attention core
    attn_kernel<<<BB, 256, 179328>>>(ab, th1w, th1b, th2w, th2b);
    // 4. attn@V + depthwise conv + GELU
    out_kernel<<<dim3(HEADS, BB), 224>>>();
    // 5. output projection (384 x 49 per batch, K=1024)
    gemm_kernel<<<dim3(3, BB), 224>>>((const float*)pgpw, (const float*)pgpb,
                                      (const float*)pghid, (float*)d_out, DIMC, DHC);
}

// round 8
// speedup vs baseline: 1.7367x; 1.7367x over previous
#include <cuda_runtime.h>
#include <math.h>

#define BB 1024
#define DIMC 384
#define NN 49
#define HEADS 8
#define KD 32
#define DV 128
#define DHC 1024
#define CQKV 1536

// ---------------- scratch (static device allocations) ----------------
__device__ float g_w[CQKV * DIMC];              // fused qkv weights (BN + scale folded)
__device__ float g_bias[CQKV];
__device__ float g_pw[DIMC * DHC];              // fused proj weights
__device__ float g_pb[DIMC];
__device__ float g_vlw[DHC * 9];                // fused depthwise weights
__device__ float g_vlb[DHC];
__device__ float g_qkv[(size_t)BB * CQKV * NN];     // 308 MB
__device__ float g_hidden[(size_t)BB * DHC * NN];   // 205 MB

// ---------------- tf32 mma helpers ----------------
__device__ __forceinline__ unsigned cvt_tf32(float f) {
    unsigned r;
    asm("cvt.rna.tf32.f32 %0, %1;" : "=r"(r) : "f"(f));
    return r;
}
__device__ __forceinline__ void mma8(float* d, const unsigned* a, unsigned b0, unsigned b1) {
    asm("mma.sync.aligned.m16n8k8.row.col.f32.tf32.tf32.f32 "
        "{%0,%1,%2,%3},{%4,%5,%6,%7},{%8,%9},{%0,%1,%2,%3};"
        : "+f"(d[0]), "+f"(d[1]), "+f"(d[2]), "+f"(d[3])
        : "r"(a[0]), "r"(a[1]), "r"(a[2]), "r"(a[3]), "r"(b0), "r"(b1));
}

// ---------------- prep: fold BN affines / scales into weights ----------------
__global__ void prep_kernel(const float* __restrict__ qw, const float* __restrict__ qb,
                            const float* __restrict__ qs, const float* __restrict__ qo,
                            const float* __restrict__ kw, const float* __restrict__ kb,
                            const float* __restrict__ ks, const float* __restrict__ ko,
                            const float* __restrict__ vw, const float* __restrict__ vb,
                            const float* __restrict__ vs, const float* __restrict__ vo,
                            const float* __restrict__ vlw, const float* __restrict__ vlb,
                            const float* __restrict__ vls, const float* __restrict__ vlo,
                            const float* __restrict__ pw, const float* __restrict__ pb,
                            const float* __restrict__ ps, const float* __restrict__ po) {
    int i = blockIdx.x * blockDim.x + threadIdx.x;
    const float SCALE = 0.17677669529663687f;  // 32^-0.5, folded into q
    if (i < CQKV * DIMC) {
        int o = i / DIMC, c = i - o * DIMC;
        float v;
        if (o < 256)       v = qw[o * DIMC + c] * qs[o] * SCALE;
        else if (o < 512)  { int oo = o - 256; v = kw[oo * DIMC + c] * ks[oo]; }
        else               { int oo = o - 512; v = vw[oo * DIMC + c] * vs[oo]; }
        g_w[i] = v;
    }
    if (i < CQKV) {
        float v;
        if (i < 256)       v = (qb[i] * qs[i] + qo[i]) * SCALE;
        else if (i < 512)  { int oo = i - 256; v = kb[oo] * ks[oo] + ko[oo]; }
        else               { int oo = i - 512; v = vb[oo] * vs[oo] + vo[oo]; }
        g_bias[i] = v;
    }
    if (i < DIMC * DHC) { int o = i / DHC; g_pw[i] = pw[i] * ps[o]; }
    if (i < DIMC)  g_pb[i] = pb[i] * ps[i] + po[i];
    if (i < DHC * 9) { int c = i / 9; g_vlw[i] = vlw[i] * vls[c]; }
    if (i < DHC)   g_vlb[i] = vlb[i] * vls[i] + vlo[i];
}

// ---------------- tensor-core GEMM: Y[b,o,n] = sum_c W[o,c]*X[b,c,n] + bias[o] ----
// mma.sync m16n8k8 tf32. Block: 128 threads (4 warps). Block tile M=128 x N=49.
// Warp tile: M=32 (2 m-tiles) x N=56 (7 n-tiles, cols >=49 are zero-padded).
__global__ __launch_bounds__(128) void gemm_tc(const float* __restrict__ W,
                                               const float* __restrict__ bias,
                                               const float* __restrict__ X,
                                               float* __restrict__ Y, int O, int K) {
    __shared__ unsigned ws[128][36];   // W tile, tf32 bits; pad 36 -> conflict-free A frags
    __shared__ unsigned xs[32][56];    // X tile, tf32 bits; stride 56 -> conflict-free B frags
    __shared__ float bs[128];
    int b = blockIdx.y;
    int obase = blockIdx.x * 128;
    const float* Xb = X + (size_t)b * K * NN;
    float* Yb = Y + (size_t)b * O * NN;
    int tid = threadIdx.x;
    int warp = tid >> 5, lane = tid & 31;
    int g = lane >> 2, t = lane & 3;
    int m0 = warp * 32;

    float acc[2][7][4];
#pragma unroll
    for (int mt = 0; mt < 2; mt++)
#pragma unroll
        for (int nt = 0; nt < 7; nt++)
#pragma unroll
            for (int x = 0; x < 4; x++) acc[mt][nt][x] = 0.f;

    bs[tid] = bias[obase + tid];
    // zero the N-pad columns (49..55) once; never rewritten
    for (int i = tid; i < 32 * 7; i += 128) xs[i / 7][49 + i % 7] = 0u;

    for (int c0 = 0; c0 < K; c0 += 32) {
        __syncthreads();
        // W tile: 128x32 floats -> tf32, vectorized float4 loads
        for (int i = tid; i < 1024; i += 128) {
            int o = i >> 3, c4 = (i & 7) << 2;
            float4 v = *(const float4*)&W[(size_t)(obase + o) * K + c0 + c4];
            ws[o][c4 + 0] = cvt_tf32(v.x);
            ws[o][c4 + 1] = cvt_tf32(v.y);
            ws[o][c4 + 2] = cvt_tf32(v.z);
            ws[o][c4 + 3] = cvt_tf32(v.w);
        }
        // X tile: 32x49
        for (int i = tid; i < 32 * NN; i += 128) {
            int cc = i / NN, n = i - cc * NN;
            xs[cc][n] = cvt_tf32(Xb[(size_t)(c0 + cc) * NN + n]);
        }
        __syncthreads();
#pragma unroll
        for (int kk = 0; kk < 32; kk += 8) {
            unsigned a[2][4];
#pragma unroll
            for (int mt = 0; mt < 2; mt++) {
                int r = m0 + mt * 16;
                a[mt][0] = ws[r + g][kk + t];
                a[mt][1] = ws[r + 8 + g][kk + t];
                a[mt][2] = ws[r + g][kk + t + 4];
                a[mt][3] = ws[r + 8 + g][kk + t + 4];
            }
#pragma unroll
            for (int nt = 0; nt < 7; nt++) {
                unsigned b0 = xs[kk + t][nt * 8 + g];
                unsigned b1 = xs[kk + t + 4][nt * 8 + g];
                mma8(acc[0][nt], a[0], b0, b1);
                mma8(acc[1][nt], a[1], b0, b1);
            }
        }
    }

    // epilogue: D row = m0 + mt*16 + g (+8), col = nt*8 + 2t (+1)
#pragma unroll
    for (int mt = 0; mt < 2; mt++) {
        int r0 = m0 + mt * 16 + g;
        float bv0 = bs[r0], bv1 = bs[r0 + 8];
        size_t base0 = (size_t)(obase + r0) * NN;
        size_t base1 = (size_t)(obase + r0 + 8) * NN;
#pragma unroll
        for (int nt = 0; nt < 7; nt++) {
            int col = nt * 8 + 2 * t;
            if (col < NN) {
                Yb[base0 + col] = acc[mt][nt][0] + bv0;
                Yb[base1 + col] = acc[mt][nt][2] + bv1;
            }
            if (col + 1 < NN) {
                Yb[base0 + col + 1] = acc[mt][nt][1] + bv0;
                Yb[base1 + col + 1] = acc[mt][nt][3] + bv1;
            }
        }
    }
}

// ---------------- fused attention core + attn@V + depthwise + GELU ----------------
// one block per batch. Phases:
//  1. load q,k -> r1 (25088 f)
//  2. scores + rel-pos bias -> r2 (19208 f)
//  3. th1 head-mix: r2 -> r1 (q/k dead)
//  4. softmax rows in r1
//  5. th2 head-mix: r1 -> r2 (raw scores dead)
//  6. per head h: stage V_h into r1 (softmax data dead), attn@V + depthwise conv
//     + exact GELU -> g_hidden
__global__ __launch_bounds__(256) void attn_out_kernel(const float* __restrict__ ab,
                                                       const float* __restrict__ th1w_g,
                                                       const float* __restrict__ th1b_g,
                                                       const float* __restrict__ th2w_g,
                                                       const float* __restrict__ th2b_g) {
    extern __shared__ float sm[];
    float* r1 = sm;                 // 25088 floats
    float* r2 = sm + 25088;         // 19208 floats
    float* abs_ = sm + 44296;       // 392
    float* t1w = abs_ + 392;        // 64
    float* t1b = t1w + 64;          // 8
    float* t2w = t1b + 8;           // 64
    float* t2b = t2w + 64;          // 8
    int b = blockIdx.x;
    int tid = threadIdx.x;
    const float* qkbase = g_qkv + (size_t)b * CQKV * NN;  // channels 0..511 = q,k

    for (int i = tid; i < (512 * NN) / 4; i += 256)
        ((float4*)r1)[i] = ((const float4*)qkbase)[i];
    for (int i = tid; i < 392; i += 256) abs_[i] = ab[i];
    if (tid < 64) { t1w[tid] = th1w_g[tid]; t2w[tid] = th2w_g[tid]; }
    if (tid < 8)  { t1b[tid] = th1b_g[tid]; t2b[tid] = th2b_g[tid]; }
    __syncthreads();

    // scores: r2[h,n,m] = q·k (scale folded into q) + rel-pos bias
    for (int p = tid; p < HEADS * NN; p += 256) {
        int h = p / NN, n = p - h * NN;
        float qv[KD];
#pragma unroll
        for (int kd = 0; kd < KD; kd++) qv[kd] = r1[(h * KD + kd) * NN + n];
        int ny = n / 7, nx = n - ny * 7;
        const float* kb_ = r1 + (256 + h * KD) * NN;
        float* srow = r2 + (size_t)h * NN * NN + n * NN;
        const float* abh = abs_ + h * NN;
        for (int m = 0; m < NN; m++) {
            float s = 0.f;
#pragma unroll
            for (int kd = 0; kd < KD; kd++) s += qv[kd] * kb_[kd * NN + m];
            int my = m / 7, mx = m - my * 7;
            int ridx = abs(ny - my) * 7 + abs(nx - mx);
            srow[m] = s + abh[ridx];
        }
    }
    __syncthreads();

    // th1 head mix -> r1 (q/k space reused)
    for (int p = tid; p < HEADS * NN; p += 256) {
        int i = p / NN, n = p - i * NN;
        float w[8];
#pragma unroll
        for (int j = 0; j < 8; j++) w[j] = t1w[i * 8 + j];
        float bi = t1b[i];
        const float* base = r2 + n * NN;
        float* orow = r1 + (size_t)p * NN;
        for (int m = 0; m < NN; m++) {
            float s = bi;
#pragma unroll
            for (int j = 0; j < 8; j++) s += w[j] * base[j * 2401 + m];
            orow[m] = s;
        }
    }
    __syncthreads();

    // softmax in place (rows of 49)
    for (int p = tid; p < HEADS * NN; p += 256) {
        float* row = r1 + (size_t)p * NN;
        float mx = row[0];
        for (int m = 1; m < NN; m++) mx = fmaxf(mx, row[m]);
        float sum = 0.f;
        for (int m = 0; m < NN; m++) { float e = __expf(row[m] - mx); row[m] = e; sum += e; }
        float inv = 1.f / sum;
        for (int m = 0; m < NN; m++) row[m] *= inv;
    }
    __syncthreads();

    // th2 head mix -> r2 (raw scores dead)
    for (int p = tid; p < HEADS * NN; p += 256) {
        int i = p / NN, n = p - i * NN;
        float w[8];
#pragma unroll
        for (int j = 0; j < 8; j++) w[j] = t2w[i * 8 + j];
        float bi = t2b[i];
        const float* base = r1 + n * NN;
        float* orow = r2 + (size_t)i * 2401 + n * NN;
        for (int m = 0; m < NN; m++) {
            float s = bi;
#pragma unroll
            for (int j = 0; j < 8; j++) s += w[j] * base[j * 2401 + m];
            orow[m] = s;
        }
    }

    // per-head: attn@V + depthwise conv + GELU (V staged in r1)
    int dg = tid / 7, y = tid - dg * 7;   // dg 0..35 (use <32), y 0..6
    int d0 = dg * 4;
    for (int h = 0; h < HEADS; h++) {
        __syncthreads();  // prev head compute done (and th2 done on first iter)
        const float* vp = g_qkv + (size_t)b * CQKV * NN + (size_t)(512 + h * DV) * NN;
        for (int i = tid; i < (DV * NN) / 4; i += 256)
            ((float4*)r1)[i] = ((const float4*)vp)[i];
        __syncthreads();
        if (dg < 32) {
            const float* as_ = r2 + (size_t)h * NN * NN;  // [n*49 + m]
            float acc[7][4];
#pragma unroll
            for (int x = 0; x < 7; x++)
#pragma unroll
                for (int j = 0; j < 4; j++) acc[x][j] = 0.f;

            for (int m = 0; m < NN; m++) {
                float a[7];
#pragma unroll
                for (int x = 0; x < 7; x++) a[x] = as_[(y * 7 + x) * NN + m];
#pragma unroll
                for (int j = 0; j < 4; j++) {
                    float v = r1[(d0 + j) * NN + m];
#pragma unroll
                    for (int x = 0; x < 7; x++) acc[x][j] += a[x] * v;
                }
            }

            float* hb = g_hidden + (size_t)b * DHC * NN + (size_t)(h * DV) * NN;
#pragma unroll
            for (int j = 0; j < 4; j++) {
                int d = d0 + j;
                int c = h * DV + d;
                float wv[9];
#pragma unroll
                for (int k2 = 0; k2 < 9; k2++) wv[k2] = g_vlw[c * 9 + k2];
                float vb_ = g_vlb[c];
#pragma unroll
                for (int x = 0; x < 7; x++) {
                    float vl = vb_;
#pragma unroll
                    for (int dy = -1; dy <= 1; dy++) {
                        int yy = y + dy;
                        if (yy < 0 || yy >= 7) continue;
#pragma unroll
                        for (int dx = -1; dx <= 1; dx++) {
                            int xx = x + dx;
                            if (xx < 0 || xx >= 7) continue;
                            vl += wv[(dy + 1) * 3 + (dx + 1)] * r1[d * NN + yy * 7 + xx];
                        }
                    }
                    float o = acc[x][j] + vl;
                    o = o * normcdff(o);  // exact GELU
                    hb[(size_t)d * NN + y * 7 + x] = o;
                }
            }
        }
    }
}

// ---------------- host ----------------
extern "C" void kernel_launch(void* const* d_in, const int* in_sizes, int n_in,
                              void* d_out, int out_size) {
    const float* x    = (const float*)d_in[0];
    const float* qw   = (const float*)d_in[1];
    const float* qb   = (const float*)d_in[2];
    const float* qs   = (const float*)d_in[3];
    const float* qo   = (const float*)d_in[4];
    const float* kw   = (const float*)d_in[5];
    const float* kb   = (const float*)d_in[6];
    const float* ks   = (const float*)d_in[7];
    const float* ko   = (const float*)d_in[8];
    const float* vw   = (const float*)d_in[9];
    const float* vb   = (const float*)d_in[10];
    const float* vs   = (const float*)d_in[11];
    const float* vo   = (const float*)d_in[12];
    const float* vlw  = (const float*)d_in[13];
    const float* vlb  = (const float*)d_in[14];
    const float* vls  = (const float*)d_in[15];
    const float* vlo  = (const float*)d_in[16];
    const float* th1w = (const float*)d_in[17];
    const float* th1b = (const float*)d_in[18];
    const float* th2w = (const float*)d_in[19];
    const float* th2b = (const float*)d_in[20];
    const float* pw   = (const float*)d_in[21];
    const float* pb   = (const float*)d_in[22];
    const float* ps   = (const float*)d_in[23];
    const float* po   = (const float*)d_in[24];
    const float* ab   = (const float*)d_in[25];

    void *pgw, *pgbias, *pgpw, *pgpb, *pgqkv, *pghid;
    cudaGetSymbolAddress(&pgw, g_w);
    cudaGetSymbolAddress(&pgbias, g_bias);
    cudaGetSymbolAddress(&pgpw, g_pw);
    cudaGetSymbolAddress(&pgpb, g_pb);
    cudaGetSymbolAddress(&pgqkv, g_qkv);
    cudaGetSymbolAddress(&pghid, g_hidden);

    cudaFuncSetAttribute(attn_out_kernel, cudaFuncAttributeMaxDynamicSharedMemorySize, 179328);

    // 1. fold affines into weights
    prep_kernel<<<(CQKV * DIMC + 255) / 256, 256>>>(qw, qb, qs, qo, kw, kb, ks, ko,
                                                    vw, vb, vs, vo, vlw, vlb, vls, vlo,
                                                    pw, pb, ps, po);
    // 2. fused QKV projection (1536 x 49 per batch, K=384) — tensor cores
    gemm_tc<<<dim3(12, BB), 128>>>((const float*)pgw, (const float*)pgbias, x,
                                   (float*)pgqkv, CQKV, DIMC);
    // 3. fused attention core + attn@V + depthwise + GELU
    attn_out_kernel<<<BB, 256, 179328>>>(ab, th1w, th1b, th2w, th2b);
    // 4. output projection (384 x 49 per batch, K=1024) — tensor cores
    gemm_tc<<<dim3(3, BB), 128>>>((const float*)pgpw, (const float*)pgpb,
                                  (const float*)pghid, (float*)d_out, DIMC, DHC);
}

// round 9
// speedup vs baseline: 2.0458x; 1.1780x over previous
#include <cuda_runtime.h>
#include <math.h>

#define BB 1024
#define DIMC 384
#define NN 49
#define HEADS 8
#define KD 32
#define DV 128
#define DHC 1024
#define CQKV 1536

// ---------------- scratch (static device allocations) ----------------
__device__ float g_w[CQKV * DIMC];              // fused qkv weights, tf32-rounded bits
__device__ float g_bias[CQKV];
__device__ float g_pw[DIMC * DHC];              // fused proj weights, tf32-rounded bits
__device__ float g_pb[DIMC];
__device__ float g_vlw[DHC * 9];                // fused depthwise weights
__device__ float g_vlb[DHC];
__device__ float g_qkv[(size_t)BB * CQKV * NN];     // 308 MB
__device__ float g_hidden[(size_t)BB * DHC * NN];   // 205 MB

// ---------------- tf32 mma helpers ----------------
__device__ __forceinline__ unsigned cvt_tf32(float f) {
    unsigned r;
    asm("cvt.rna.tf32.f32 %0, %1;" : "=r"(r) : "f"(f));
    return r;
}
__device__ __forceinline__ void mma8(float* d, const unsigned* a, unsigned b0, unsigned b1) {
    asm("mma.sync.aligned.m16n8k8.row.col.f32.tf32.tf32.f32 "
        "{%0,%1,%2,%3},{%4,%5,%6,%7},{%8,%9},{%0,%1,%2,%3};"
        : "+f"(d[0]), "+f"(d[1]), "+f"(d[2]), "+f"(d[3])
        : "r"(a[0]), "r"(a[1]), "r"(a[2]), "r"(a[3]), "r"(b0), "r"(b1));
}

// ---------------- prep: fold BN affines / scales into weights (tf32-round GEMM W) ----
__global__ void prep_kernel(const float* __restrict__ qw, const float* __restrict__ qb,
                            const float* __restrict__ qs, const float* __restrict__ qo,
                            const float* __restrict__ kw, const float* __restrict__ kb,
                            const float* __restrict__ ks, const float* __restrict__ ko,
                            const float* __restrict__ vw, const float* __restrict__ vb,
                            const float* __restrict__ vs, const float* __restrict__ vo,
                            const float* __restrict__ vlw, const float* __restrict__ vlb,
                            const float* __restrict__ vls, const float* __restrict__ vlo,
                            const float* __restrict__ pw, const float* __restrict__ pb,
                            const float* __restrict__ ps, const float* __restrict__ po) {
    int i = blockIdx.x * blockDim.x + threadIdx.x;
    const float SCALE = 0.17677669529663687f;  // 32^-0.5, folded into q
    if (i < CQKV * DIMC) {
        int o = i / DIMC, c = i - o * DIMC;
        float v;
        if (o < 256)       v = qw[o * DIMC + c] * qs[o] * SCALE;
        else if (o < 512)  { int oo = o - 256; v = kw[oo * DIMC + c] * ks[oo]; }
        else               { int oo = o - 512; v = vw[oo * DIMC + c] * vs[oo]; }
        g_w[i] = __uint_as_float(cvt_tf32(v));
    }
    if (i < CQKV) {
        float v;
        if (i < 256)       v = (qb[i] * qs[i] + qo[i]) * SCALE;
        else if (i < 512)  { int oo = i - 256; v = kb[oo] * ks[oo] + ko[oo]; }
        else               { int oo = i - 512; v = vb[oo] * vs[oo] + vo[oo]; }
        g_bias[i] = v;
    }
    if (i < DIMC * DHC) { int o = i / DHC; g_pw[i] = __uint_as_float(cvt_tf32(pw[i] * ps[o])); }
    if (i < DIMC)  g_pb[i] = pb[i] * ps[i] + po[i];
    if (i < DHC * 9) { int c = i / 9; g_vlw[i] = vlw[i] * vls[c]; }
    if (i < DHC)   g_vlb[i] = vlb[i] * vls[i] + vlo[i];
}

// ---------------- tensor-core GEMM: Y[b,o,n] = sum_c W[o,c]*X[b,c,n] + bias[o] ----
// mma.sync m16n8k8 tf32. 256 threads (8 warps), block tile M=128 x N=49,
// warp tile m16 x n56 (7 n-tiles). SMEM layouts use a k-permutation within
// groups of 8 (k -> (k&~7)|((k&3)<<1)|((k&7)>>2)) so that the (k, k+4)
// fragment pairs sit adjacent -> LDS.64 for both A and B fragments.
__global__ __launch_bounds__(256) void gemm_tc(const unsigned* __restrict__ W,
                                               const float* __restrict__ bias,
                                               const float* __restrict__ X,
                                               float* __restrict__ Y, int O, int K) {
    __shared__ unsigned ws[128][36];   // [o][k-permuted]
    __shared__ unsigned xs[56][36];    // [n][k-permuted]; rows 49..55 zero
    __shared__ float bs[128];
    int b = blockIdx.y;
    int obase = blockIdx.x * 128;
    const float* Xb = X + (size_t)b * K * NN;
    float* Yb = Y + (size_t)b * O * NN;
    int tid = threadIdx.x;
    int warp = tid >> 5, lane = tid & 31;
    int g = lane >> 2, t = lane & 3;
    int m0 = warp * 16;

    float acc[7][4];
#pragma unroll
    for (int nt = 0; nt < 7; nt++)
#pragma unroll
        for (int x = 0; x < 4; x++) acc[nt][x] = 0.f;

    if (tid < 128) bs[tid] = bias[obase + tid];
    for (int i = tid; i < 7 * 36; i += 256) xs[49 + i / 36][i % 36] = 0u;

    // X-fill mapping: 32x49 tile is a contiguous span of 1568 floats starting
    // at Xb + c0*NN. Each thread's slots are chunk-invariant; precompute once.
    unsigned short soff[7], goff[7];
    int nfill = 0;
#pragma unroll 1
    for (int i = tid; i < 32 * NN; i += 256) {
        int cc = i / NN, n = i - cc * NN;
        int kp = (cc & ~7) | ((cc & 3) << 1) | ((cc & 7) >> 2);
        soff[nfill] = (unsigned short)(n * 36 + kp);
        goff[nfill] = (unsigned short)i;
        nfill++;
    }
    unsigned* xsf = &xs[0][0];

    for (int c0 = 0; c0 < K; c0 += 32) {
        __syncthreads();
        // W tile: 128x32 tf32 words, k-permuted scatter (4 scalar STS per uint4)
        for (int i = tid; i < 1024; i += 256) {
            int o = i >> 3, c4 = (i & 7) << 2;   // c4 in {0,4,8,...,28}
            uint4 v = *(const uint4*)&W[(size_t)(obase + o) * K + c0 + c4];
            int base = (c4 & ~7) | ((c4 & 4) >> 2);
            ws[o][base + 0] = v.x;
            ws[o][base + 2] = v.y;
            ws[o][base + 4] = v.z;
            ws[o][base + 6] = v.w;
        }
        // X tile via precomputed mapping (cvt to tf32 here; X is fp32)
        const float* xsrc = Xb + (size_t)c0 * NN;
#pragma unroll
        for (int j = 0; j < 7; j++)
            if (j < nfill) xsf[soff[j]] = cvt_tf32(xsrc[goff[j]]);
        __syncthreads();
#pragma unroll
        for (int kk8 = 0; kk8 < 4; kk8++) {
            int kc = kk8 * 8 + 2 * t;
            uint2 a02 = *(const uint2*)&ws[m0 + g][kc];       // a0, a2
            uint2 a13 = *(const uint2*)&ws[m0 + 8 + g][kc];   // a1, a3
            unsigned a[4] = {a02.x, a13.x, a02.y, a13.y};
#pragma unroll
            for (int nt = 0; nt < 7; nt++) {
                uint2 bb = *(const uint2*)&xs[nt * 8 + g][kc];
                mma8(acc[nt], a, bb.x, bb.y);
            }
        }
    }

    // epilogue: D row = m0 + g (+8), col = nt*8 + 2t (+1)
    int r0 = m0 + g;
    float bv0 = bs[r0], bv1 = bs[r0 + 8];
    size_t base0 = (size_t)(obase + r0) * NN;
    size_t base1 = (size_t)(obase + r0 + 8) * NN;
#pragma unroll
    for (int nt = 0; nt < 7; nt++) {
        int col = nt * 8 + 2 * t;
        if (col < NN) {
            Yb[base0 + col] = acc[nt][0] + bv0;
            Yb[base1 + col] = acc[nt][2] + bv1;
        }
        if (col + 1 < NN) {
            Yb[base0 + col + 1] = acc[nt][1] + bv0;
            Yb[base1 + col + 1] = acc[nt][3] + bv1;
        }
    }
}

// ---------------- fused attention core + attn@V + depthwise + GELU ----------------
__global__ __launch_bounds__(256) void attn_out_kernel(const float* __restrict__ ab,
                                                       const float* __restrict__ th1w_g,
                                                       const float* __restrict__ th1b_g,
                                                       const float* __restrict__ th2w_g,
                                                       const float* __restrict__ th2b_g) {
    extern __shared__ float sm[];
    float* r1 = sm;                 // 25088 floats
    float* r2 = sm + 25088;         // 19208 floats
    float* abs_ = sm + 44296;       // 392
    float* t1w = abs_ + 392;        // 64
    float* t1b = t1w + 64;          // 8
    float* t2w = t1b + 8;           // 64
    float* t2b = t2w + 64;          // 8
    int b = blockIdx.x;
    int tid = threadIdx.x;
    const float* qkbase = g_qkv + (size_t)b * CQKV * NN;  // channels 0..511 = q,k

    for (int i = tid; i < (512 * NN) / 4; i += 256)
        ((float4*)r1)[i] = ((const float4*)qkbase)[i];
    for (int i = tid; i < 392; i += 256) abs_[i] = ab[i];
    if (tid < 64) { t1w[tid] = th1w_g[tid]; t2w[tid] = th2w_g[tid]; }
    if (tid < 8)  { t1b[tid] = th1b_g[tid]; t2b[tid] = th2b_g[tid]; }
    __syncthreads();

    // scores: r2[h,n,m] = q·k (scale folded into q) + rel-pos bias
    for (int p = tid; p < HEADS * NN; p += 256) {
        int h = p / NN, n = p - h * NN;
        float qv[KD];
#pragma unroll
        for (int kd = 0; kd < KD; kd++) qv[kd] = r1[(h * KD + kd) * NN + n];
        int ny = n / 7, nx = n - ny * 7;
        const float* kb_ = r1 + (256 + h * KD) * NN;
        float* srow = r2 + (size_t)h * NN * NN + n * NN;
        const float* abh = abs_ + h * NN;
        for (int m = 0; m < NN; m++) {
            float s = 0.f;
#pragma unroll
            for (int kd = 0; kd < KD; kd++) s += qv[kd] * kb_[kd * NN + m];
            int my = m / 7, mx = m - my * 7;
            int ridx = abs(ny - my) * 7 + abs(nx - mx);
            srow[m] = s + abh[ridx];
        }
    }
    __syncthreads();

    // th1 head mix -> r1 (q/k space reused)
    for (int p = tid; p < HEADS * NN; p += 256) {
        int i = p / NN, n = p - i * NN;
        float w[8];
#pragma unroll
        for (int j = 0; j < 8; j++) w[j] = t1w[i * 8 + j];
        float bi = t1b[i];
        const float* base = r2 + n * NN;
        float* orow = r1 + (size_t)p * NN;
        for (int m = 0; m < NN; m++) {
            float s = bi;
#pragma unroll
            for (int j = 0; j < 8; j++) s += w[j] * base[j * 2401 + m];
            orow[m] = s;
        }
    }
    __syncthreads();

    // softmax in place (rows of 49)
    for (int p = tid; p < HEADS * NN; p += 256) {
        float* row = r1 + (size_t)p * NN;
        float mx = row[0];
        for (int m = 1; m < NN; m++) mx = fmaxf(mx, row[m]);
        float sum = 0.f;
        for (int m = 0; m < NN; m++) { float e = __expf(row[m] - mx); row[m] = e; sum += e; }
        float inv = 1.f / sum;
        for (int m = 0; m < NN; m++) row[m] *= inv;
    }
    __syncthreads();

    // th2 head mix -> r2 (raw scores dead)
    for (int p = tid; p < HEADS * NN; p += 256) {
        int i = p / NN, n = p - i * NN;
        float w[8];
#pragma unroll
        for (int j = 0; j < 8; j++) w[j] = t2w[i * 8 + j];
        float bi = t2b[i];
        const float* base = r1 + n * NN;
        float* orow = r2 + (size_t)i * 2401 + n * NN;
        for (int m = 0; m < NN; m++) {
            float s = bi;
#pragma unroll
            for (int j = 0; j < 8; j++) s += w[j] * base[j * 2401 + m];
            orow[m] = s;
        }
    }

    // per-head: attn@V + depthwise conv + GELU (V staged in r1)
    int dg = tid / 7, y = tid - dg * 7;   // dg 0..36 (use <32), y 0..6
    int d0 = dg * 4;
    for (int h = 0; h < HEADS; h++) {
        __syncthreads();  // prev head compute done (and th2 done on first iter)
        const float* vp = g_qkv + (size_t)b * CQKV * NN + (size_t)(512 + h * DV) * NN;
        for (int i = tid; i < (DV * NN) / 4; i += 256)
            ((float4*)r1)[i] = ((const float4*)vp)[i];
        __syncthreads();
        if (dg < 32) {
            const float* as_ = r2 + (size_t)h * NN * NN;  // [n*49 + m]
            float acc[7][4];
#pragma unroll
            for (int x = 0; x < 7; x++)
#pragma unroll
                for (int j = 0; j < 4; j++) acc[x][j] = 0.f;

            for (int m = 0; m < NN; m++) {
                float a[7];
#pragma unroll
                for (int x = 0; x < 7; x++) a[x] = as_[(y * 7 + x) * NN + m];
#pragma unroll
                for (int j = 0; j < 4; j++) {
                    float v = r1[(d0 + j) * NN + m];
#pragma unroll
                    for (int x = 0; x < 7; x++) acc[x][j] += a[x] * v;
                }
            }

            float* hb = g_hidden + (size_t)b * DHC * NN + (size_t)(h * DV) * NN;
#pragma unroll
            for (int j = 0; j < 4; j++) {
                int d = d0 + j;
                int c = h * DV + d;
                float wv[9];
#pragma unroll
                for (int k2 = 0; k2 < 9; k2++) wv[k2] = g_vlw[c * 9 + k2];
                float vb_ = g_vlb[c];
#pragma unroll
                for (int x = 0; x < 7; x++) {
                    float vl = vb_;
#pragma unroll
                    for (int dy = -1; dy <= 1; dy++) {
                        int yy = y + dy;
                        if (yy < 0 || yy >= 7) continue;
#pragma unroll
                        for (int dx = -1; dx <= 1; dx++) {
                            int xx = x + dx;
                            if (xx < 0 || xx >= 7) continue;
                            vl += wv[(dy + 1) * 3 + (dx + 1)] * r1[d * NN + yy * 7 + xx];
                        }
                    }
                    float o = acc[x][j] + vl;
                    o = o * normcdff(o);  // exact GELU
                    hb[(size_t)d * NN + y * 7 + x] = o;
                }
            }
        }
    }
}

// ---------------- host ----------------
extern "C" void kernel_launch(void* const* d_in, const int* in_sizes, int n_in,
                              void* d_out, int out_size) {
    const float* x    = (const float*)d_in[0];
    const float* qw   = (const float*)d_in[1];
    const float* qb   = (const float*)d_in[2];
    const float* qs   = (const float*)d_in[3];
    const float* qo   = (const float*)d_in[4];
    const float* kw   = (const float*)d_in[5];
    const float* kb   = (const float*)d_in[6];
    const float* ks   = (const float*)d_in[7];
    const float* ko   = (const float*)d_in[8];
    const float* vw   = (const float*)d_in[9];
    const float* vb   = (const float*)d_in[10];
    const float* vs   = (const float*)d_in[11];
    const float* vo   = (const float*)d_in[12];
    const float* vlw  = (const float*)d_in[13];
    const float* vlb  = (const float*)d_in[14];
    const float* vls  = (const float*)d_in[15];
    const float* vlo  = (const float*)d_in[16];
    const float* th1w = (const float*)d_in[17];
    const float* th1b = (const float*)d_in[18];
    const float* th2w = (const float*)d_in[19];
    const float* th2b = (const float*)d_in[20];
    const float* pw   = (const float*)d_in[21];
    const float* pb   = (const float*)d_in[22];
    const float* ps   = (const float*)d_in[23];
    const float* po   = (const float*)d_in[24];
    const float* ab   = (const float*)d_in[25];

    void *pgw, *pgbias, *pgpw, *pgpb, *pgqkv, *pghid;
    cudaGetSymbolAddress(&pgw, g_w);
    cudaGetSymbolAddress(&pgbias, g_bias);
    cudaGetSymbolAddress(&pgpw, g_pw);
    cudaGetSymbolAddress(&pgpb, g_pb);
    cudaGetSymbolAddress(&pgqkv, g_qkv);
    cudaGetSymbolAddress(&pghid, g_hidden);

    cudaFuncSetAttribute(attn_out_kernel, cudaFuncAttributeMaxDynamicSharedMemorySize, 179328);

    // 1. fold affines into weights (GEMM weights pre-rounded to tf32)
    prep_kernel<<<(CQKV * DIMC + 255) / 256, 256>>>(qw, qb, qs, qo, kw, kb, ks, ko,
                                                    vw, vb, vs, vo, vlw, vlb, vls, vlo,
                                                    pw, pb, ps, po);
    // 2. fused QKV projection (1536 x 49 per batch, K=384) — tensor cores
    gemm_tc<<<dim3(12, BB), 256>>>((const unsigned*)pgw, (const float*)pgbias, x,
                                   (float*)pgqkv, CQKV, DIMC);
    // 3. fused attention core + attn@V + depthwise + GELU
    attn_out_kernel<<<BB, 256, 179328>>>(ab, th1w, th1b, th2w, th2b);
    // 4. output projection (384 x 49 per batch, K=1024) — tensor cores
    gemm_tc<<<dim3(3, BB), 256>>>((const unsigned*)pgpw, (const float*)pgpb,
                                  (const float*)pghid, (float*)d_out, DIMC, DHC);
}

// round 10
// speedup vs baseline: 2.5041x; 1.2240x over previous
#include <cuda_runtime.h>
#include <math.h>

#define BB 1024
#define DIMC 384
#define NN 49
#define HEADS 8
#define KD 32
#define DV 128
#define DHC 1024
#define CQKV 1536

// k-permutation within groups of 8: k -> (k&~7) | ((k&3)<<1) | ((k>>2)&1)
// puts (k, k+4) fragment pairs adjacent for LDS.64.
#define KPERM(k) (((k) & ~7) | (((k) & 3) << 1) | ((((k) >> 2)) & 1))

// ---------------- scratch (static device allocations) ----------------
__device__ unsigned g_w[CQKV * DIMC];           // fused qkv weights, tf32 bits, k-permuted
__device__ float g_bias[CQKV];
__device__ unsigned g_pw[DIMC * DHC];           // fused proj weights, tf32 bits, k-permuted
__device__ float g_pb[DIMC];
__device__ float g_vlw[DHC * 9];                // fused depthwise weights
__device__ float g_vlb[DHC];
__device__ unsigned g_xt[(size_t)BB * NN * DIMC];   // x transposed [b][n][c], tf32 bits (77 MB)
__device__ float g_qkv[(size_t)BB * CQKV * NN];     // 308 MB
__device__ unsigned g_ht[(size_t)BB * NN * DHC];    // hidden transposed [b][n][d], tf32 (205 MB)

// ---------------- tf32 mma helpers ----------------
__device__ __forceinline__ unsigned cvt_tf32(float f) {
    unsigned r;
    asm("cvt.rna.tf32.f32 %0, %1;" : "=r"(r) : "f"(f));
    return r;
}
__device__ __forceinline__ void mma8(float* d, unsigned a0, unsigned a1, unsigned a2,
                                     unsigned a3, unsigned b0, unsigned b1) {
    asm("mma.sync.aligned.m16n8k8.row.col.f32.tf32.tf32.f32 "
        "{%0,%1,%2,%3},{%4,%5,%6,%7},{%8,%9},{%0,%1,%2,%3};"
        : "+f"(d[0]), "+f"(d[1]), "+f"(d[2]), "+f"(d[3])
        : "r"(a0), "r"(a1), "r"(a2), "r"(a3), "r"(b0), "r"(b1));
}

// ---------------- prep: fold BN affines / scales into weights ----------------
// GEMM weights: tf32-rounded AND k-permuted (so GEMM tile fill is a verbatim copy).
__global__ void prep_kernel(const float* __restrict__ qw, const float* __restrict__ qb,
                            const float* __restrict__ qs, const float* __restrict__ qo,
                            const float* __restrict__ kw, const float* __restrict__ kb,
                            const float* __restrict__ ks, const float* __restrict__ ko,
                            const float* __restrict__ vw, const float* __restrict__ vb,
                            const float* __restrict__ vs, const float* __restrict__ vo,
                            const float* __restrict__ vlw, const float* __restrict__ vlb,
                            const float* __restrict__ vls, const float* __restrict__ vlo,
                            const float* __restrict__ pw, const float* __restrict__ pb,
                            const float* __restrict__ ps, const float* __restrict__ po) {
    int i = blockIdx.x * blockDim.x + threadIdx.x;
    const float SCALE = 0.17677669529663687f;  // 32^-0.5, folded into q
    if (i < CQKV * DIMC) {
        int o = i / DIMC, c = i - o * DIMC;
        float v;
        if (o < 256)       v = qw[o * DIMC + c] * qs[o] * SCALE;
        else if (o < 512)  { int oo = o - 256; v = kw[oo * DIMC + c] * ks[oo]; }
        else               { int oo = o - 512; v = vw[oo * DIMC + c] * vs[oo]; }
        g_w[o * DIMC + KPERM(c)] = cvt_tf32(v);
    }
    if (i < CQKV) {
        float v;
        if (i < 256)       v = (qb[i] * qs[i] + qo[i]) * SCALE;
        else if (i < 512)  { int oo = i - 256; v = kb[oo] * ks[oo] + ko[oo]; }
        else               { int oo = i - 512; v = vb[oo] * vs[oo] + vo[oo]; }
        g_bias[i] = v;
    }
    if (i < DIMC * DHC) {
        int o = i / DHC, c = i - o * DHC;
        g_pw[o * DHC + KPERM(c)] = cvt_tf32(pw[i] * ps[o]);
    }
    if (i < DIMC)  g_pb[i] = pb[i] * ps[i] + po[i];
    if (i < DHC * 9) { int c = i / 9; g_vlw[i] = vlw[i] * vls[c]; }
    if (i < DHC)   g_vlb[i] = vlb[i] * vls[i] + vlo[i];
}

// ---------------- transpose x: [b][c][n] fp32 -> [b][n][c] tf32 bits ----------------
__global__ __launch_bounds__(256) void xt_kernel(const float* __restrict__ x) {
    extern __shared__ float sx[];  // 384*49 floats
    int b = blockIdx.x;
    int tid = threadIdx.x;
    const float* xb = x + (size_t)b * DIMC * NN;
    for (int i = tid; i < DIMC * NN; i += 256) sx[i] = xb[i];
    __syncthreads();
    unsigned* ob = g_xt + (size_t)b * NN * DIMC;
    for (int i = tid; i < NN * DIMC; i += 256) {
        int n = i / DIMC, c = i - n * DIMC;
        ob[i] = cvt_tf32(sx[c * NN + n]);
    }
}

// ---------------- tensor-core GEMM: Y[b,o,n] = sum_c W[o,c]*X[b,n,c] + bias[o] ----
// mma.sync m16n8k8 tf32. 128 threads (4 warps), block tile M=128 x N=49.
// Warp tile M=32 (2 m-tiles) x N=56 (7 n-tiles). Row stride 40 words (== 8 mod 32):
// A-frag LDS.64 conflict-free per phase; B-frag = 2x LDS.32, banks 8g+t all distinct.
// W is pre-permuted tf32 in gmem; X is transposed tf32 in gmem -> fills are uint4 copies.
__global__ __launch_bounds__(128) void gemm_tc(const unsigned* __restrict__ W,
                                               const float* __restrict__ bias,
                                               const unsigned* __restrict__ Xt,
                                               float* __restrict__ Y, int O, int K) {
    __shared__ unsigned ws[128][40];   // [o][k-permuted], stride 40
    __shared__ unsigned xs[56][40];    // [n][k natural], rows 49..55 zero
    __shared__ float bs[128];
    int b = blockIdx.y;
    int obase = blockIdx.x * 128;
    const unsigned* Xb = Xt + (size_t)b * NN * K;
    float* Yb = Y + (size_t)b * O * NN;
    int tid = threadIdx.x;
    int warp = tid >> 5, lane = tid & 31;
    int g = lane >> 2, t = lane & 3;
    int m0 = warp * 32;

    float acc[2][7][4];
#pragma unroll
    for (int mt = 0; mt < 2; mt++)
#pragma unroll
        for (int nt = 0; nt < 7; nt++)
#pragma unroll
            for (int x = 0; x < 4; x++) acc[mt][nt][x] = 0.f;

    bs[tid] = bias[obase + tid];
    for (int i = tid; i < 7 * 40; i += 128) xs[49 + i / 40][i % 40] = 0u;

    for (int c0 = 0; c0 < K; c0 += 32) {
        __syncthreads();
        // W tile: verbatim uint4 copy (already tf32 + permuted)
        for (int i = tid; i < 1024; i += 128) {
            int o = i >> 3, c4 = (i & 7) << 2;
            *(uint4*)&ws[o][c4] = *(const uint4*)&W[(size_t)(obase + o) * K + c0 + c4];
        }
        // X tile: verbatim uint4 copy from transposed tf32 tensor
        for (int i = tid; i < 392; i += 128) {
            int n = i >> 3, c4 = (i & 7) << 2;
            *(uint4*)&xs[n][c4] = *(const uint4*)&Xb[(size_t)n * K + c0 + c4];
        }
        __syncthreads();
#pragma unroll
        for (int kk8 = 0; kk8 < 4; kk8++) {
            int kc = kk8 * 8 + 2 * t;   // permuted pair offset
            int kn = kk8 * 8 + t;       // natural k offset
            uint2 p0 = *(const uint2*)&ws[m0 + g][kc];        // mt0: a0, a2
            uint2 p1 = *(const uint2*)&ws[m0 + 8 + g][kc];    // mt0: a1, a3
            uint2 p2 = *(const uint2*)&ws[m0 + 16 + g][kc];   // mt1: a0, a2
            uint2 p3 = *(const uint2*)&ws[m0 + 24 + g][kc];   // mt1: a1, a3
#pragma unroll
            for (int nt = 0; nt < 7; nt++) {
                unsigned b0 = xs[nt * 8 + g][kn];
                unsigned b1 = xs[nt * 8 + g][kn + 4];
                mma8(acc[0][nt], p0.x, p1.x, p0.y, p1.y, b0, b1);
                mma8(acc[1][nt], p2.x, p3.x, p2.y, p3.y, b0, b1);
            }
        }
    }

    // epilogue: D row = m0 + mt*16 + g (+8), col = nt*8 + 2t (+1)
#pragma unroll
    for (int mt = 0; mt < 2; mt++) {
        int r0 = m0 + mt * 16 + g;
        float bv0 = bs[r0], bv1 = bs[r0 + 8];
        size_t base0 = (size_t)(obase + r0) * NN;
        size_t base1 = (size_t)(obase + r0 + 8) * NN;
#pragma unroll
        for (int nt = 0; nt < 7; nt++) {
            int col = nt * 8 + 2 * t;
            if (col < NN) {
                Yb[base0 + col] = acc[mt][nt][0] + bv0;
                Yb[base1 + col] = acc[mt][nt][2] + bv1;
            }
            if (col + 1 < NN) {
                Yb[base0 + col + 1] = acc[mt][nt][1] + bv0;
                Yb[base1 + col + 1] = acc[mt][nt][3] + bv1;
            }
        }
    }
}

// ---------------- fused attention core + attn@V + depthwise + GELU ----------------
// output goes to g_ht transposed [b][n][d] as tf32 bits (feeds proj GEMM directly).
__global__ __launch_bounds__(256) void attn_out_kernel(const float* __restrict__ ab,
                                                       const float* __restrict__ th1w_g,
                                                       const float* __restrict__ th1b_g,
                                                       const float* __restrict__ th2w_g,
                                                       const float* __restrict__ th2b_g) {
    extern __shared__ float sm[];
    float* r1 = sm;                 // 25088 floats
    float* r2 = sm + 25088;         // 19208 floats
    float* abs_ = sm + 44296;       // 392
    float* t1w = abs_ + 392;        // 64
    float* t1b = t1w + 64;          // 8
    float* t2w = t1b + 8;           // 64
    float* t2b = t2w + 64;          // 8
    int b = blockIdx.x;
    int tid = threadIdx.x;
    const float* qkbase = g_qkv + (size_t)b * CQKV * NN;  // channels 0..511 = q,k

    for (int i = tid; i < (512 * NN) / 4; i += 256)
        ((float4*)r1)[i] = ((const float4*)qkbase)[i];
    for (int i = tid; i < 392; i += 256) abs_[i] = ab[i];
    if (tid < 64) { t1w[tid] = th1w_g[tid]; t2w[tid] = th2w_g[tid]; }
    if (tid < 8)  { t1b[tid] = th1b_g[tid]; t2b[tid] = th2b_g[tid]; }
    __syncthreads();

    // scores: r2[h,n,m] = q·k (scale folded into q) + rel-pos bias
    for (int p = tid; p < HEADS * NN; p += 256) {
        int h = p / NN, n = p - h * NN;
        float qv[KD];
#pragma unroll
        for (int kd = 0; kd < KD; kd++) qv[kd] = r1[(h * KD + kd) * NN + n];
        int ny = n / 7, nx = n - ny * 7;
        const float* kb_ = r1 + (256 + h * KD) * NN;
        float* srow = r2 + (size_t)h * NN * NN + n * NN;
        const float* abh = abs_ + h * NN;
        for (int m = 0; m < NN; m++) {
            float s = 0.f;
#pragma unroll
            for (int kd = 0; kd < KD; kd++) s += qv[kd] * kb_[kd * NN + m];
            int my = m / 7, mx = m - my * 7;
            int ridx = abs(ny - my) * 7 + abs(nx - mx);
            srow[m] = s + abh[ridx];
        }
    }
    __syncthreads();

    // th1 head mix -> r1 (q/k space reused)
    for (int p = tid; p < HEADS * NN; p += 256) {
        int i = p / NN, n = p - i * NN;
        float w[8];
#pragma unroll
        for (int j = 0; j < 8; j++) w[j] = t1w[i * 8 + j];
        float bi = t1b[i];
        const float* base = r2 + n * NN;
        float* orow = r1 + (size_t)p * NN;
        for (int m = 0; m < NN; m++) {
            float s = bi;
#pragma unroll
            for (int j = 0; j < 8; j++) s += w[j] * base[j * 2401 + m];
            orow[m] = s;
        }
    }
    __syncthreads();

    // softmax in place (rows of 49)
    for (int p = tid; p < HEADS * NN; p += 256) {
        float* row = r1 + (size_t)p * NN;
        float mx = row[0];
        for (int m = 1; m < NN; m++) mx = fmaxf(mx, row[m]);
        float sum = 0.f;
        for (int m = 0; m < NN; m++) { float e = __expf(row[m] - mx); row[m] = e; sum += e; }
        float inv = 1.f / sum;
        for (int m = 0; m < NN; m++) row[m] *= inv;
    }
    __syncthreads();

    // th2 head mix -> r2 (raw scores dead)
    for (int p = tid; p < HEADS * NN; p += 256) {
        int i = p / NN, n = p - i * NN;
        float w[8];
#pragma unroll
        for (int j = 0; j < 8; j++) w[j] = t2w[i * 8 + j];
        float bi = t2b[i];
        const float* base = r1 + n * NN;
        float* orow = r2 + (size_t)i * 2401 + n * NN;
        for (int m = 0; m < NN; m++) {
            float s = bi;
#pragma unroll
            for (int j = 0; j < 8; j++) s += w[j] * base[j * 2401 + m];
            orow[m] = s;
        }
    }

    // per-head: attn@V + depthwise conv + GELU (V staged in r1) -> g_ht transposed tf32
    int dg = tid / 7, y = tid - dg * 7;   // dg 0..36 (use <32), y 0..6
    int d0 = dg * 4;
    for (int h = 0; h < HEADS; h++) {
        __syncthreads();  // prev head compute done (and th2 done on first iter)
        const float* vp = g_qkv + (size_t)b * CQKV * NN + (size_t)(512 + h * DV) * NN;
        for (int i = tid; i < (DV * NN) / 4; i += 256)
            ((float4*)r1)[i] = ((const float4*)vp)[i];
        __syncthreads();
        if (dg < 32) {
            const float* as_ = r2 + (size_t)h * NN * NN;  // [n*49 + m]
            float acc[7][4];
#pragma unroll
            for (int x = 0; x < 7; x++)
#pragma unroll
                for (int j = 0; j < 4; j++) acc[x][j] = 0.f;

            for (int m = 0; m < NN; m++) {
                float a[7];
#pragma unroll
                for (int x = 0; x < 7; x++) a[x] = as_[(y * 7 + x) * NN + m];
#pragma unroll
                for (int j = 0; j < 4; j++) {
                    float v = r1[(d0 + j) * NN + m];
#pragma unroll
                    for (int x = 0; x < 7; x++) acc[x][j] += a[x] * v;
                }
            }

            // depthwise conv + GELU into acc
#pragma unroll
            for (int j = 0; j < 4; j++) {
                int d = d0 + j;
                int c = h * DV + d;
                float wv[9];
#pragma unroll
                for (int k2 = 0; k2 < 9; k2++) wv[k2] = g_vlw[c * 9 + k2];
                float vb_ = g_vlb[c];
#pragma unroll
                for (int x = 0; x < 7; x++) {
                    float vl = vb_;
#pragma unroll
                    for (int dy = -1; dy <= 1; dy++) {
                        int yy = y + dy;
                        if (yy < 0 || yy >= 7) continue;
#pragma unroll
                        for (int dx = -1; dx <= 1; dx++) {
                            int xx = x + dx;
                            if (xx < 0 || xx >= 7) continue;
                            vl += wv[(dy + 1) * 3 + (dx + 1)] * r1[d * NN + yy * 7 + xx];
                        }
                    }
                    float o = acc[x][j] + vl;
                    acc[x][j] = o * normcdff(o);  // exact GELU
                }
            }

            // store transposed tf32: g_ht[b][n][h*DV + d0 .. +3] via STG.128
            unsigned* hrow = g_ht + ((size_t)b * NN) * DHC + h * DV + d0;
#pragma unroll
            for (int x = 0; x < 7; x++) {
                int n = y * 7 + x;
                uint4 pk;
                pk.x = cvt_tf32(acc[x][0]);
                pk.y = cvt_tf32(acc[x][1]);
                pk.z = cvt_tf32(acc[x][2]);
                pk.w = cvt_tf32(acc[x][3]);
                *(uint4*)&hrow[(size_t)n * DHC] = pk;
            }
        }
    }
}

// ---------------- host ----------------
extern "C" void kernel_launch(void* const* d_in, const int* in_sizes, int n_in,
                              void* d_out, int out_size) {
    const float* x    = (const float*)d_in[0];
    const float* qw   = (const float*)d_in[1];
    const float* qb   = (const float*)d_in[2];
    const float* qs   = (const float*)d_in[3];
    const float* qo   = (const float*)d_in[4];
    const float* kw   = (const float*)d_in[5];
    const float* kb   = (const float*)d_in[6];
    const float* ks   = (const float*)d_in[7];
    const float* ko   = (const float*)d_in[8];
    const float* vw   = (const float*)d_in[9];
    const float* vb   = (const float*)d_in[10];
    const float* vs   = (const float*)d_in[11];
    const float* vo   = (const float*)d_in[12];
    const float* vlw  = (const float*)d_in[13];
    const float* vlb  = (const float*)d_in[14];
    const float* vls  = (const float*)d_in[15];
    const float* vlo  = (const float*)d_in[16];
    const float* th1w = (const float*)d_in[17];
    const float* th1b = (const float*)d_in[18];
    const float* th2w = (const float*)d_in[19];
    const float* th2b = (const float*)d_in[20];
    const float* pw   = (const float*)d_in[21];
    const float* pb   = (const float*)d_in[22];
    const float* ps   = (const float*)d_in[23];
    const float* po   = (const float*)d_in[24];
    const float* ab   = (const float*)d_in[25];

    void *pgw, *pgbias, *pgpw, *pgpb, *pgxt, *pgqkv, *pght;
    cudaGetSymbolAddress(&pgw, g_w);
    cudaGetSymbolAddress(&pgbias, g_bias);
    cudaGetSymbolAddress(&pgpw, g_pw);
    cudaGetSymbolAddress(&pgpb, g_pb);
    cudaGetSymbolAddress(&pgxt, g_xt);
    cudaGetSymbolAddress(&pgqkv, g_qkv);
    cudaGetSymbolAddress(&pght, g_ht);

    cudaFuncSetAttribute(attn_out_kernel, cudaFuncAttributeMaxDynamicSharedMemorySize, 179328);
    cudaFuncSetAttribute(xt_kernel, cudaFuncAttributeMaxDynamicSharedMemorySize, 75264);

    // 1. fold affines into weights (tf32 + k-permuted)
    prep_kernel<<<(CQKV * DIMC + 255) / 256, 256>>>(qw, qb, qs, qo, kw, kb, ks, ko,
                                                    vw, vb, vs, vo, vlw, vlb, vls, vlo,
                                                    pw, pb, ps, po);
    // 1b. transpose x -> [b][n][c] tf32
    xt_kernel<<<BB, 256, 75264>>>(x);
    // 2. fused QKV projection (1536 x 49 per batch, K=384) — tensor cores
    gemm_tc<<<dim3(12, BB), 128>>>((const unsigned*)pgw, (const float*)pgbias,
                                   (const unsigned*)pgxt, (float*)pgqkv, CQKV, DIMC);
    // 3. fused attention core + attn@V + depthwise + GELU -> hidden transposed tf32
    attn_out_kernel<<<BB, 256, 179328>>>(ab, th1w, th1b, th2w, th2b);
    // 4. output projection (384 x 49 per batch, K=1024) — tensor cores
    gemm_tc<<<dim3(3, BB), 128>>>((const unsigned*)pgpw, (const float*)pgpb,
                                  (const unsigned*)pght, (float*)d_out, DIMC, DHC);
}